// round 1
// baseline (speedup 1.0000x reference)
#include <cuda_runtime.h>
#include <math.h>

// Problem dims (fixed by setup_inputs)
#define NN 2048   // nodes
#define BB 32     // batch
#define DD 64     // hidden dim
#define D2 128    // 2*hidden
#define EE 10     // embed dim
#define KK 3      // cheb order
#define PG (KK*DD*D2)   // 24576 — per-node gate weight elems
#define PU (KK*D2*DD)   // 24576 — per-node update weight elems

// -------- device scratch (static allocation — no runtime allocs) --------
__device__ float g_adj[NN*NN];        // 16 MB
__device__ float g_Xt [NN*BB*DD];     // x transposed to (N,B,D)
__device__ float g_G1 [NN*BB*DD];     // adj @ Xt
__device__ float g_G2 [NN*BB*DD];     // 2*adj@G1 - Xt
__device__ float g_R  [NN*BB*DD];     // gate r
__device__ float g_C  [NN*BB*D2];     // candidate [x, z]   (N,B,2D)
__device__ float g_H1 [NN*BB*D2];     // adj @ C
__device__ float g_H2 [NN*BB*D2];     // 2*adj@H1 - C
__device__ float g_Wg [NN*PG];        // per-node gate weights   (~201 MB)
__device__ float g_Wu [NN*PU];        // per-node update weights (~201 MB)
__device__ float g_Bg [NN*D2];
__device__ float g_Bu [NN*DD];

// =====================================================================
// adj = softmax(relu(emb @ emb^T), axis=1) — one block per row
// =====================================================================
__global__ __launch_bounds__(256) void adj_kernel(const float* __restrict__ emb) {
    __shared__ float row[NN];
    __shared__ float red[256];
    const int n = blockIdx.x;
    const int tid = threadIdx.x;

    float en[EE];
#pragma unroll
    for (int e = 0; e < EE; e++) en[e] = emb[n*EE + e];

    float lmax = 0.f;
    for (int m = tid; m < NN; m += 256) {
        float s = 0.f;
#pragma unroll
        for (int e = 0; e < EE; e++) s = fmaf(en[e], emb[m*EE + e], s);
        s = fmaxf(s, 0.f);
        row[m] = s;
        lmax = fmaxf(lmax, s);
    }
    red[tid] = lmax; __syncthreads();
    for (int s = 128; s > 0; s >>= 1) {
        if (tid < s) red[tid] = fmaxf(red[tid], red[tid + s]);
        __syncthreads();
    }
    const float gmax = red[0];
    __syncthreads();

    float lsum = 0.f;
    for (int m = tid; m < NN; m += 256) {
        float v = __expf(row[m] - gmax);
        row[m] = v;
        lsum += v;
    }
    red[tid] = lsum; __syncthreads();
    for (int s = 128; s > 0; s >>= 1) {
        if (tid < s) red[tid] += red[tid + s];
        __syncthreads();
    }
    const float inv = 1.f / red[0];
    for (int m = tid; m < NN; m += 256) g_adj[n*NN + m] = row[m] * inv;
}

// =====================================================================
// Transpose x (B,N,D) -> Xt (N,B,D); also fill first half of candidate C
// =====================================================================
__global__ __launch_bounds__(256) void transpose_kernel(const float* __restrict__ x) {
    int idx = blockIdx.x * 256 + threadIdx.x;   // over N*B*16 float4s
    int d4 = idx & 15;
    int b  = (idx >> 4) & 31;
    int n  = idx >> 9;
    float4 v = *(const float4*)&x[((size_t)b*NN + n)*DD + d4*4];
    *(float4*)&g_Xt[((size_t)n*BB + b)*DD + d4*4] = v;
    *(float4*)&g_C [((size_t)n*BB + b)*D2 + d4*4] = v;
}

// =====================================================================
// Per-node weight materialization: W[n, j] = sum_e emb[n,e]*pool[e, j]
// (P = 24576 for both pools). Grid: (P/256, N/256)
// =====================================================================
__device__ __forceinline__ void wgen_body(const float* __restrict__ emb,
                                          const float* __restrict__ pool,
                                          float* __restrict__ out) {
    __shared__ float ps[EE][256];
    const int j = blockIdx.x * 256 + threadIdx.x;
    const int nbase = blockIdx.y * 256;
#pragma unroll
    for (int e = 0; e < EE; e++) ps[e][threadIdx.x] = pool[e*PG + j];
    __syncthreads();
    for (int n = nbase; n < nbase + 256; n++) {
        float acc = 0.f;
#pragma unroll
        for (int e = 0; e < EE; e++) acc = fmaf(emb[n*EE + e], ps[e][threadIdx.x], acc);
        out[(size_t)n*PG + j] = acc;
    }
}
__global__ __launch_bounds__(256) void wgen_gate(const float* emb, const float* pool) { wgen_body(emb, pool, g_Wg); }
__global__ __launch_bounds__(256) void wgen_upd (const float* emb, const float* pool) { wgen_body(emb, pool, g_Wu); }

// bias: out[n,p] = sum_e emb[n,e] * bpool[e,p]
__device__ __forceinline__ void bgen_body(const float* __restrict__ emb,
                                          const float* __restrict__ bpool,
                                          float* __restrict__ out, int P) {
    int idx = blockIdx.x * 256 + threadIdx.x;
    if (idx >= NN * P) return;
    int n = idx / P, p = idx - n * P;
    float acc = 0.f;
#pragma unroll
    for (int e = 0; e < EE; e++) acc = fmaf(emb[n*EE + e], bpool[e*P + p], acc);
    out[idx] = acc;
}
__global__ __launch_bounds__(256) void bgen_gate(const float* emb, const float* bp) { bgen_body(emb, bp, g_Bg, D2); }
__global__ __launch_bounds__(256) void bgen_upd (const float* emb, const float* bp) { bgen_body(emb, bp, g_Bu, DD); }

// =====================================================================
// SGEMM: Out = alpha * (A @ B) + beta * Csrc
// A = g_adj (2048 x 2048 row-major), B/Out/Csrc are 2048 x Mcols
// 128x128x16 block tile, 8x8 thread tile, 256 threads
// =====================================================================
#define GBM 128
#define GBN 128
#define GBK 16
__device__ __forceinline__ void sgemm_body(const float* __restrict__ A,
                                           const float* __restrict__ B,
                                           float* __restrict__ Out,
                                           const float* __restrict__ Cs,
                                           float alpha, float beta, int Mcols) {
    __shared__ float As[GBK][GBM + 4];   // +4 pad: de-conflict transpose store
    __shared__ float Bs[GBK][GBN];

    const int tid = threadIdx.x;
    const int rowBase = blockIdx.y * GBM;
    const int colBase = blockIdx.x * GBN;

    const int aRow = tid >> 2;          // 0..63
    const int aCol = (tid & 3) * 4;     // 0,4,8,12
    const int bRow = tid >> 5;          // 0..7
    const int bCol = (tid & 31) * 4;    // 0..124

    const int tx = tid & 15;
    const int ty = tid >> 4;

    float acc[8][8] = {};

    for (int k0 = 0; k0 < NN; k0 += GBK) {
#pragma unroll
        for (int r = 0; r < 2; r++) {
            float4 v = *(const float4*)&A[(size_t)(rowBase + aRow + r*64)*NN + k0 + aCol];
            As[aCol + 0][aRow + r*64] = v.x;
            As[aCol + 1][aRow + r*64] = v.y;
            As[aCol + 2][aRow + r*64] = v.z;
            As[aCol + 3][aRow + r*64] = v.w;
        }
#pragma unroll
        for (int r = 0; r < 2; r++) {
            float4 v = *(const float4*)&B[(size_t)(k0 + bRow + r*8)*Mcols + colBase + bCol];
            *(float4*)&Bs[bRow + r*8][bCol] = v;
        }
        __syncthreads();
#pragma unroll
        for (int kk = 0; kk < GBK; kk++) {
            float ra[8], rb[8];
            *(float4*)&ra[0] = *(const float4*)&As[kk][ty*8];
            *(float4*)&ra[4] = *(const float4*)&As[kk][ty*8 + 4];
            *(float4*)&rb[0] = *(const float4*)&Bs[kk][tx*8];
            *(float4*)&rb[4] = *(const float4*)&Bs[kk][tx*8 + 4];
#pragma unroll
            for (int i = 0; i < 8; i++)
#pragma unroll
                for (int j = 0; j < 8; j++)
                    acc[i][j] = fmaf(ra[i], rb[j], acc[i][j]);
        }
        __syncthreads();
    }

#pragma unroll
    for (int i = 0; i < 8; i++) {
        size_t row = rowBase + ty*8 + i;
#pragma unroll
        for (int j = 0; j < 8; j += 4) {
            size_t col = colBase + tx*8 + j;
            float4 r;
            r.x = alpha * acc[i][j + 0];
            r.y = alpha * acc[i][j + 1];
            r.z = alpha * acc[i][j + 2];
            r.w = alpha * acc[i][j + 3];
            if (Cs) {
                float4 c = *(const float4*)&Cs[row*Mcols + col];
                r.x = fmaf(beta, c.x, r.x);
                r.y = fmaf(beta, c.y, r.y);
                r.z = fmaf(beta, c.z, r.z);
                r.w = fmaf(beta, c.w, r.w);
            }
            *(float4*)&Out[row*Mcols + col] = r;
        }
    }
}
__global__ __launch_bounds__(256) void sgemm_g1() { sgemm_body(g_adj, g_Xt, g_G1, nullptr, 1.f,  0.f, BB*DD); }
__global__ __launch_bounds__(256) void sgemm_g2() { sgemm_body(g_adj, g_G1, g_G2, g_Xt,   2.f, -1.f, BB*DD); }
__global__ __launch_bounds__(256) void sgemm_h1() { sgemm_body(g_adj, g_C,  g_H1, nullptr, 1.f,  0.f, BB*D2); }
__global__ __launch_bounds__(256) void sgemm_h2() { sgemm_body(g_adj, g_H1, g_H2, g_C,    2.f, -1.f, BB*D2); }

// =====================================================================
// Gate mix: per node n (block), zr[b,o] = [Xt|G1|G2]_n (32x192) @ W_n (192x128) + Bg
// z = sigmoid(zr[:, :64]) -> C second half ; r = sigmoid(zr[:, 64:]) -> g_R
// =====================================================================
#define JLDG 193   // padded row stride for A tile (192 -> 193, de-bank)
__global__ __launch_bounds__(256) void gate_mix_kernel() {
    extern __shared__ float sm[];
    float* Ws = sm;              // PG floats = 96 KB
    float* Av = sm + PG;         // 32 * JLDG floats

    const int n = blockIdx.x;
    const int tid = threadIdx.x;

    // stage per-node weights
    const float4* wsrc = (const float4*)(g_Wg + (size_t)n * PG);
    float4* wdst = (float4*)Ws;
    for (int i = tid; i < PG/4; i += 256) wdst[i] = wsrc[i];

    // stage 3 k-slices of x_g:  A[b][k*64+i]
    const float* s0 = g_Xt + (size_t)n * (BB*DD);
    const float* s1 = g_G1 + (size_t)n * (BB*DD);
    const float* s2 = g_G2 + (size_t)n * (BB*DD);
    for (int t = tid; t < BB*DD; t += 256) {
        int b = t >> 6, i = t & 63;
        Av[b*JLDG +   0 + i] = s0[t];
        Av[b*JLDG +  64 + i] = s1[t];
        Av[b*JLDG + 128 + i] = s2[t];
    }
    __syncthreads();

    const int tx = tid & 31;   // o-groups of 4 -> 128 outputs
    const int ty = tid >> 5;   // b-groups of 4 -> 32 batches
    float acc[4][4] = {};

#pragma unroll 4
    for (int j = 0; j < KK*DD; j++) {
        float4 wv = *(const float4*)&Ws[j*D2 + tx*4];
        float a0 = Av[(ty*4 + 0)*JLDG + j];
        float a1 = Av[(ty*4 + 1)*JLDG + j];
        float a2 = Av[(ty*4 + 2)*JLDG + j];
        float a3 = Av[(ty*4 + 3)*JLDG + j];
        acc[0][0] = fmaf(a0, wv.x, acc[0][0]); acc[0][1] = fmaf(a0, wv.y, acc[0][1]);
        acc[0][2] = fmaf(a0, wv.z, acc[0][2]); acc[0][3] = fmaf(a0, wv.w, acc[0][3]);
        acc[1][0] = fmaf(a1, wv.x, acc[1][0]); acc[1][1] = fmaf(a1, wv.y, acc[1][1]);
        acc[1][2] = fmaf(a1, wv.z, acc[1][2]); acc[1][3] = fmaf(a1, wv.w, acc[1][3]);
        acc[2][0] = fmaf(a2, wv.x, acc[2][0]); acc[2][1] = fmaf(a2, wv.y, acc[2][1]);
        acc[2][2] = fmaf(a2, wv.z, acc[2][2]); acc[2][3] = fmaf(a2, wv.w, acc[2][3]);
        acc[3][0] = fmaf(a3, wv.x, acc[3][0]); acc[3][1] = fmaf(a3, wv.y, acc[3][1]);
        acc[3][2] = fmaf(a3, wv.z, acc[3][2]); acc[3][3] = fmaf(a3, wv.w, acc[3][3]);
    }

#pragma unroll
    for (int bb = 0; bb < 4; bb++) {
        int b = ty*4 + bb;
#pragma unroll
        for (int oo = 0; oo < 4; oo++) {
            int o = tx*4 + oo;
            float v = acc[bb][oo] + g_Bg[n*D2 + o];
            float s = 1.f / (1.f + __expf(-v));
            if (o < DD)
                g_C[((size_t)n*BB + b)*D2 + DD + o] = s;       // z -> candidate
            else
                g_R[((size_t)n*BB + b)*DD + (o - DD)] = s;     // r
        }
    }
}

// =====================================================================
// Update mix: hc = tanh([C|H1|H2]_n (32x384) @ Wu_n (384x64) + Bu)
// h = r*x + (1-r)*hc -> d_out (B,N,D)
// =====================================================================
#define JLDU 385
__global__ __launch_bounds__(256) void update_mix_kernel(float* __restrict__ out) {
    extern __shared__ float sm[];
    float* Ws = sm;              // PU floats = 96 KB
    float* Av = sm + PU;         // 32 * JLDU floats

    const int n = blockIdx.x;
    const int tid = threadIdx.x;

    const float4* wsrc = (const float4*)(g_Wu + (size_t)n * PU);
    float4* wdst = (float4*)Ws;
    for (int i = tid; i < PU/4; i += 256) wdst[i] = wsrc[i];

    const float* s0 = g_C  + (size_t)n * (BB*D2);
    const float* s1 = g_H1 + (size_t)n * (BB*D2);
    const float* s2 = g_H2 + (size_t)n * (BB*D2);
    for (int t = tid; t < BB*D2; t += 256) {
        int b = t >> 7, i = t & 127;
        Av[b*JLDU +   0 + i] = s0[t];
        Av[b*JLDU + 128 + i] = s1[t];
        Av[b*JLDU + 256 + i] = s2[t];
    }
    __syncthreads();

    const int tx = tid & 15;   // o-groups of 4 -> 64 outputs
    const int ty = tid >> 4;   // b-groups of 2 -> 32 batches
    float acc[2][4] = {};

#pragma unroll 4
    for (int j = 0; j < KK*D2; j++) {
        float4 wv = *(const float4*)&Ws[j*DD + tx*4];
        float a0 = Av[(ty*2 + 0)*JLDU + j];
        float a1 = Av[(ty*2 + 1)*JLDU + j];
        acc[0][0] = fmaf(a0, wv.x, acc[0][0]); acc[0][1] = fmaf(a0, wv.y, acc[0][1]);
        acc[0][2] = fmaf(a0, wv.z, acc[0][2]); acc[0][3] = fmaf(a0, wv.w, acc[0][3]);
        acc[1][0] = fmaf(a1, wv.x, acc[1][0]); acc[1][1] = fmaf(a1, wv.y, acc[1][1]);
        acc[1][2] = fmaf(a1, wv.z, acc[1][2]); acc[1][3] = fmaf(a1, wv.w, acc[1][3]);
    }

#pragma unroll
    for (int bb = 0; bb < 2; bb++) {
        int b = ty*2 + bb;
#pragma unroll
        for (int oo = 0; oo < 4; oo++) {
            int o = tx*4 + oo;
            float v  = acc[bb][oo] + g_Bu[n*DD + o];
            float hc = tanhf(v);
            float r  = g_R [((size_t)n*BB + b)*DD + o];
            float xv = g_Xt[((size_t)n*BB + b)*DD + o];
            out[(size_t)b*(NN*DD) + (size_t)n*DD + o] = fmaf(r, xv - hc, hc);
        }
    }
}

// =====================================================================
// Launch
// =====================================================================
extern "C" void kernel_launch(void* const* d_in, const int* in_sizes, int n_in,
                              void* d_out, int out_size) {
    const float* x   = (const float*)d_in[0];
    // d_in[1] = state (unused by the reference)
    const float* emb = (const float*)d_in[2];
    const float* gwp = (const float*)d_in[3];
    const float* gbp = (const float*)d_in[4];
    const float* uwp = (const float*)d_in[5];
    const float* ubp = (const float*)d_in[6];
    float* out = (float*)d_out;

    const int GATE_SMEM = (PG + BB*JLDG) * 4;   // 123,008 B
    const int UPD_SMEM  = (PU + BB*JLDU) * 4;   // 147,584 B
    cudaFuncSetAttribute(gate_mix_kernel,   cudaFuncAttributeMaxDynamicSharedMemorySize, GATE_SMEM);
    cudaFuncSetAttribute(update_mix_kernel, cudaFuncAttributeMaxDynamicSharedMemorySize, UPD_SMEM);

    adj_kernel<<<NN, 256>>>(emb);
    transpose_kernel<<<(NN*BB*16)/256, 256>>>(x);

    wgen_gate<<<dim3(PG/256, NN/256), 256>>>(emb, gwp);
    wgen_upd <<<dim3(PU/256, NN/256), 256>>>(emb, uwp);
    bgen_gate<<<(NN*D2 + 255)/256, 256>>>(emb, gbp);
    bgen_upd <<<(NN*DD + 255)/256, 256>>>(emb, ubp);

    sgemm_g1<<<dim3((BB*DD)/GBN, NN/GBM), 256>>>();
    sgemm_g2<<<dim3((BB*DD)/GBN, NN/GBM), 256>>>();
    gate_mix_kernel<<<NN, 256, GATE_SMEM>>>();

    sgemm_h1<<<dim3((BB*D2)/GBN, NN/GBM), 256>>>();
    sgemm_h2<<<dim3((BB*D2)/GBN, NN/GBM), 256>>>();
    update_mix_kernel<<<NN, 256, UPD_SMEM>>>(out);
}

// round 5
// speedup vs baseline: 1.2871x; 1.2871x over previous
#include <cuda_runtime.h>
#include <cuda_bf16.h>
#include <mma.h>
#include <math.h>
#include <stdint.h>

using namespace nvcuda;

// Problem dims (fixed by setup_inputs)
#define NN 2048   // nodes
#define BB 32     // batch
#define DD 64     // hidden dim
#define D2 128    // 2*hidden
#define EE 10     // embed dim
#define KK 3      // cheb order
#define PG (KK*DD*D2)   // 24576
#define PU (KK*D2*DD)   // 24576

// WMMA GEMM tiling
#define CTM 128
#define CTN 128
#define CTK 32
#define STAGES 3
#define A_LD 48
#define B_LD 144
#define A_TILE_B (CTM*A_LD*2)        // 12288
#define B_TILE_B (CTK*B_LD*2)        // 9216
#define STAGE_B  (2*A_TILE_B + 2*B_TILE_B)  // 43008
#define HG_SMEM  (STAGES*STAGE_B)    // 129024

// -------- device scratch (static allocation — no runtime allocs) --------
__device__ float g_adj[NN*NN];        // fp32 adjacency (R1-proven path)
__device__ float g_Xt [NN*BB*DD];
__device__ float g_G1 [NN*BB*DD];
__device__ float g_G2 [NN*BB*DD];
__device__ float g_R  [NN*BB*DD];
__device__ float g_C  [NN*BB*D2];
__device__ float g_H1 [NN*BB*D2];
__device__ float g_H2 [NN*BB*D2];
__device__ float g_Wg [(size_t)NN*PG];
__device__ float g_Wu [(size_t)NN*PU];
__device__ float g_Bg [NN*D2];
__device__ float g_Bu [NN*DD];

// bf16 hi/lo split operands (layouts identical to their fp32 sources)
__device__ __align__(16) __nv_bfloat16 bAh [NN*NN];
__device__ __align__(16) __nv_bfloat16 bAl [NN*NN];
__device__ __align__(16) __nv_bfloat16 bXh [NN*BB*DD];
__device__ __align__(16) __nv_bfloat16 bXl [NN*BB*DD];
__device__ __align__(16) __nv_bfloat16 bG1h[NN*BB*DD];
__device__ __align__(16) __nv_bfloat16 bG1l[NN*BB*DD];
__device__ __align__(16) __nv_bfloat16 bCh [(size_t)NN*BB*D2];
__device__ __align__(16) __nv_bfloat16 bCl [(size_t)NN*BB*D2];
__device__ __align__(16) __nv_bfloat16 bH1h[(size_t)NN*BB*D2];
__device__ __align__(16) __nv_bfloat16 bH1l[(size_t)NN*BB*D2];

// =====================================================================
// helpers
// =====================================================================
__device__ __forceinline__ uint32_t smem_u32(const void* p) {
    uint32_t a;
    asm("{ .reg .u64 t; cvta.to.shared.u64 t, %1; cvt.u32.u64 %0, t; }" : "=r"(a) : "l"(p));
    return a;
}
#define CP16(dst, src) asm volatile("cp.async.cg.shared.global [%0], [%1], 16;" :: "r"(dst), "l"(src))
#define CP_COMMIT()    asm volatile("cp.async.commit_group;")
#define CP_WAIT1()     asm volatile("cp.async.wait_group 1;")
#define CP_WAIT0()     asm volatile("cp.async.wait_group 0;")

__device__ __forceinline__ void split2(float a, float b, uint32_t& hi, uint32_t& lo) {
    __nv_bfloat16 ah = __float2bfloat16(a), bh = __float2bfloat16(b);
    float ar = a - __bfloat162float(ah), br = b - __bfloat162float(bh);
    __nv_bfloat16 al = __float2bfloat16(ar), bl = __float2bfloat16(br);
    hi = (uint32_t)__bfloat16_as_ushort(ah) | ((uint32_t)__bfloat16_as_ushort(bh) << 16);
    lo = (uint32_t)__bfloat16_as_ushort(al) | ((uint32_t)__bfloat16_as_ushort(bl) << 16);
}

// =====================================================================
// adj = softmax(relu(emb @ emb^T), axis=1) — R1-proven, fp32 output
// =====================================================================
__global__ __launch_bounds__(256) void adj_kernel(const float* __restrict__ emb) {
    __shared__ float row[NN];
    __shared__ float red[256];
    const int n = blockIdx.x;
    const int tid = threadIdx.x;
    float en[EE];
#pragma unroll
    for (int e = 0; e < EE; e++) en[e] = emb[n*EE + e];
    float lmax = 0.f;
    for (int m = tid; m < NN; m += 256) {
        float s = 0.f;
#pragma unroll
        for (int e = 0; e < EE; e++) s = fmaf(en[e], emb[m*EE + e], s);
        s = fmaxf(s, 0.f);
        row[m] = s;
        lmax = fmaxf(lmax, s);
    }
    red[tid] = lmax; __syncthreads();
    for (int s = 128; s > 0; s >>= 1) { if (tid < s) red[tid] = fmaxf(red[tid], red[tid+s]); __syncthreads(); }
    const float gmax = red[0];
    __syncthreads();
    float lsum = 0.f;
    for (int m = tid; m < NN; m += 256) { float v = __expf(row[m] - gmax); row[m] = v; lsum += v; }
    red[tid] = lsum; __syncthreads();
    for (int s = 128; s > 0; s >>= 1) { if (tid < s) red[tid] += red[tid+s]; __syncthreads(); }
    const float inv = 1.f / red[0];
    for (int m = tid; m < NN; m += 256) g_adj[n*NN + m] = row[m] * inv;
}

// =====================================================================
// Transpose x (B,N,D) -> Xt (N,B,D); also fill first half of candidate C
// (R1-proven)
// =====================================================================
__global__ __launch_bounds__(256) void transpose_kernel(const float* __restrict__ x) {
    int idx = blockIdx.x * 256 + threadIdx.x;
    int d4 = idx & 15;
    int b  = (idx >> 4) & 31;
    int n  = idx >> 9;
    float4 v = *(const float4*)&x[((size_t)b*NN + n)*DD + d4*4];
    *(float4*)&g_Xt[((size_t)n*BB + b)*DD + d4*4] = v;
    *(float4*)&g_C [((size_t)n*BB + b)*D2 + d4*4] = v;
}

// =====================================================================
// Elementwise fp32 -> bf16 hi/lo split (linear index; layout preserved)
// sel: 0=adj, 1=Xt, 2=G1, 3=C, 4=H1
// =====================================================================
__global__ __launch_bounds__(256) void split_kernel(int sel) {
    const float* src; __nv_bfloat16 *dh, *dl;
    switch (sel) {
        case 0:  src = g_adj; dh = bAh;  dl = bAl;  break;
        case 1:  src = g_Xt;  dh = bXh;  dl = bXl;  break;
        case 2:  src = g_G1;  dh = bG1h; dl = bG1l; break;
        case 3:  src = g_C;   dh = bCh;  dl = bCl;  break;
        default: src = g_H1;  dh = bH1h; dl = bH1l; break;
    }
    size_t i = (size_t)blockIdx.x * 256 + threadIdx.x;   // float4 index
    float4 v = ((const float4*)src)[i];
    uint2 hi, lo;
    split2(v.x, v.y, hi.x, lo.x);
    split2(v.z, v.w, hi.y, lo.y);
    ((uint2*)dh)[i] = hi;
    ((uint2*)dl)[i] = lo;
}

// =====================================================================
// Per-node weight materialization (R1-proven version)
// =====================================================================
__device__ __forceinline__ void wgen_body(const float* __restrict__ emb,
                                          const float* __restrict__ pool,
                                          float* __restrict__ out) {
    __shared__ float ps[EE][256];
    const int j = blockIdx.x * 256 + threadIdx.x;
    const int nbase = blockIdx.y * 256;
#pragma unroll
    for (int e = 0; e < EE; e++) ps[e][threadIdx.x] = pool[e*PG + j];
    __syncthreads();
    for (int n = nbase; n < nbase + 256; n++) {
        float acc = 0.f;
#pragma unroll
        for (int e = 0; e < EE; e++) acc = fmaf(emb[n*EE + e], ps[e][threadIdx.x], acc);
        out[(size_t)n*PG + j] = acc;
    }
}
__global__ __launch_bounds__(256) void wgen_gate(const float* emb, const float* pool) { wgen_body(emb, pool, g_Wg); }
__global__ __launch_bounds__(256) void wgen_upd (const float* emb, const float* pool) { wgen_body(emb, pool, g_Wu); }

__device__ __forceinline__ void bgen_body(const float* __restrict__ emb,
                                          const float* __restrict__ bpool,
                                          float* __restrict__ out, int P) {
    int idx = blockIdx.x * 256 + threadIdx.x;
    if (idx >= NN * P) return;
    int n = idx / P, p = idx - n * P;
    float acc = 0.f;
#pragma unroll
    for (int e = 0; e < EE; e++) acc = fmaf(emb[n*EE + e], bpool[e*P + p], acc);
    out[idx] = acc;
}
__global__ __launch_bounds__(256) void bgen_gate(const float* emb, const float* bp) { bgen_body(emb, bp, g_Bg, D2); }
__global__ __launch_bounds__(256) void bgen_upd (const float* emb, const float* bp) { bgen_body(emb, bp, g_Bu, DD); }

// =====================================================================
// WMMA bf16-split GEMM: Out = alpha*(A@B) + beta*Cs   (fp32 output only)
// 128x128x32 tile, 8 warps (32x64 each), 3-stage cp.async pipeline
// =====================================================================
__global__ __launch_bounds__(256, 1) void hgemm_kernel(int which) {
    const __nv_bfloat16 *gBh, *gBl;
    float* Out; const float* Cs; float alpha, beta; int Ncols;
    switch (which) {
        case 0:  gBh = bXh;  gBl = bXl;  Out = g_G1; Cs = nullptr; alpha = 1.f; beta =  0.f; Ncols = 2048; break;
        case 1:  gBh = bG1h; gBl = bG1l; Out = g_G2; Cs = g_Xt;    alpha = 2.f; beta = -1.f; Ncols = 2048; break;
        case 2:  gBh = bCh;  gBl = bCl;  Out = g_H1; Cs = nullptr; alpha = 1.f; beta =  0.f; Ncols = 4096; break;
        default: gBh = bH1h; gBl = bH1l; Out = g_H2; Cs = g_C;     alpha = 2.f; beta = -1.f; Ncols = 4096; break;
    }
    extern __shared__ __align__(16) char smem[];
    const uint32_t sb = smem_u32(smem);
    const int tid  = threadIdx.x;
    const int lane = tid & 31;
    const int wid  = tid >> 5;
    const int wm   = (wid & 3) * 32;
    const int wn   = (wid >> 2) * 64;
    const int mBase = blockIdx.y * CTM;
    const int nBase = blockIdx.x * CTN;

    const int aRow = tid >> 2,  aC = tid & 3;
    const int bRow = tid >> 4,  bC = tid & 15;
    auto load_stage = [&](int it, int s) {
        const int k0 = it * CTK;
        const uint32_t st = sb + s * STAGE_B;
#pragma unroll
        for (int i = 0; i < 2; i++) {
            int row = aRow + i*64;
            uint32_t d = st + row*(A_LD*2) + aC*16;
            size_t g = (size_t)(mBase + row)*NN + k0 + aC*8;
            CP16(d,            bAh + g);
            CP16(d + A_TILE_B, bAl + g);
        }
#pragma unroll
        for (int i = 0; i < 2; i++) {
            int row = bRow + i*16;
            uint32_t d = st + 2*A_TILE_B + row*(B_LD*2) + bC*16;
            size_t g = (size_t)(k0 + row)*Ncols + nBase + bC*8;
            CP16(d,            gBh + g);
            CP16(d + B_TILE_B, gBl + g);
        }
        CP_COMMIT();
    };

    wmma::fragment<wmma::accumulator, 16, 16, 16, float> acc[2][4];
#pragma unroll
    for (int mi = 0; mi < 2; mi++)
#pragma unroll
        for (int ni = 0; ni < 4; ni++)
            wmma::fill_fragment(acc[mi][ni], 0.f);

    load_stage(0, 0);
    load_stage(1, 1);

    const int k_iters = NN / CTK;   // 64
    for (int it = 0; it < k_iters; it++) {
        const int s = it % STAGES;
        if (it + 1 < k_iters) { CP_WAIT1(); } else { CP_WAIT0(); }
        __syncthreads();
        if (it + 2 < k_iters) load_stage(it + 2, (it + 2) % STAGES);

        const __nv_bfloat16* Ah = (const __nv_bfloat16*)(smem + s*STAGE_B);
        const __nv_bfloat16* Al = Ah + CTM*A_LD;
        const __nv_bfloat16* Bh = (const __nv_bfloat16*)(smem + s*STAGE_B + 2*A_TILE_B);
        const __nv_bfloat16* Bl = Bh + CTK*B_LD;

#pragma unroll
        for (int kk = 0; kk < CTK; kk += 16) {
            wmma::fragment<wmma::matrix_a, 16, 16, 16, __nv_bfloat16, wmma::row_major> ah[2], al[2];
#pragma unroll
            for (int mi = 0; mi < 2; mi++) {
                wmma::load_matrix_sync(ah[mi], Ah + (wm + mi*16)*A_LD + kk, A_LD);
                wmma::load_matrix_sync(al[mi], Al + (wm + mi*16)*A_LD + kk, A_LD);
            }
#pragma unroll
            for (int ni = 0; ni < 4; ni++) {
                wmma::fragment<wmma::matrix_b, 16, 16, 16, __nv_bfloat16, wmma::row_major> bh, bl;
                wmma::load_matrix_sync(bh, Bh + kk*B_LD + wn + ni*16, B_LD);
                wmma::load_matrix_sync(bl, Bl + kk*B_LD + wn + ni*16, B_LD);
#pragma unroll
                for (int mi = 0; mi < 2; mi++) {
                    wmma::mma_sync(acc[mi][ni], ah[mi], bh, acc[mi][ni]);
                    wmma::mma_sync(acc[mi][ni], al[mi], bh, acc[mi][ni]);
                    wmma::mma_sync(acc[mi][ni], ah[mi], bl, acc[mi][ni]);
                }
            }
        }
        __syncthreads();
    }

    // ---- epilogue via smem staging (documented row-major layout) ----
    __syncthreads();
    float* stage = (float*)smem + wid * (32*64);
#pragma unroll
    for (int mi = 0; mi < 2; mi++)
#pragma unroll
        for (int ni = 0; ni < 4; ni++) {
            if (alpha != 1.f) {
#pragma unroll
                for (int e = 0; e < acc[mi][ni].num_elements; e++)
                    acc[mi][ni].x[e] *= alpha;
            }
            wmma::store_matrix_sync(stage + mi*16*64 + ni*16, acc[mi][ni], 64, wmma::mem_row_major);
        }
    __syncwarp();

    const int col = nBase + wn + lane*2;
    for (int r = 0; r < 32; r++) {
        const int row = mBase + wm + r;
        float2 v = *(const float2*)&stage[r*64 + lane*2];
        const size_t off = (size_t)row*Ncols + col;
        if (Cs) {
            float2 cv = *(const float2*)&Cs[off];
            v.x = fmaf(beta, cv.x, v.x);
            v.y = fmaf(beta, cv.y, v.y);
        }
        *(float2*)&Out[off] = v;
    }
}

// =====================================================================
// Gate mix (R1-proven): zr = [Xt|G1|G2]_n @ Wg_n + Bg; sigmoid
// =====================================================================
#define JLDG 193
__global__ __launch_bounds__(256) void gate_mix_kernel() {
    extern __shared__ float sm[];
    float* Ws = sm;
    float* Av = sm + PG;
    const int n = blockIdx.x;
    const int tid = threadIdx.x;

    const float4* wsrc = (const float4*)(g_Wg + (size_t)n * PG);
    float4* wdst = (float4*)Ws;
    for (int i = tid; i < PG/4; i += 256) wdst[i] = wsrc[i];

    const float* s0 = g_Xt + (size_t)n * (BB*DD);
    const float* s1 = g_G1 + (size_t)n * (BB*DD);
    const float* s2 = g_G2 + (size_t)n * (BB*DD);
    for (int t = tid; t < BB*DD; t += 256) {
        int b = t >> 6, i = t & 63;
        Av[b*JLDG +   0 + i] = s0[t];
        Av[b*JLDG +  64 + i] = s1[t];
        Av[b*JLDG + 128 + i] = s2[t];
    }
    __syncthreads();

    const int tx = tid & 31;
    const int ty = tid >> 5;
    float acc[4][4] = {};
#pragma unroll 4
    for (int j = 0; j < KK*DD; j++) {
        float4 wv = *(const float4*)&Ws[j*D2 + tx*4];
        float a0 = Av[(ty*4 + 0)*JLDG + j];
        float a1 = Av[(ty*4 + 1)*JLDG + j];
        float a2 = Av[(ty*4 + 2)*JLDG + j];
        float a3 = Av[(ty*4 + 3)*JLDG + j];
        acc[0][0] = fmaf(a0, wv.x, acc[0][0]); acc[0][1] = fmaf(a0, wv.y, acc[0][1]);
        acc[0][2] = fmaf(a0, wv.z, acc[0][2]); acc[0][3] = fmaf(a0, wv.w, acc[0][3]);
        acc[1][0] = fmaf(a1, wv.x, acc[1][0]); acc[1][1] = fmaf(a1, wv.y, acc[1][1]);
        acc[1][2] = fmaf(a1, wv.z, acc[1][2]); acc[1][3] = fmaf(a1, wv.w, acc[1][3]);
        acc[2][0] = fmaf(a2, wv.x, acc[2][0]); acc[2][1] = fmaf(a2, wv.y, acc[2][1]);
        acc[2][2] = fmaf(a2, wv.z, acc[2][2]); acc[2][3] = fmaf(a2, wv.w, acc[2][3]);
        acc[3][0] = fmaf(a3, wv.x, acc[3][0]); acc[3][1] = fmaf(a3, wv.y, acc[3][1]);
        acc[3][2] = fmaf(a3, wv.z, acc[3][2]); acc[3][3] = fmaf(a3, wv.w, acc[3][3]);
    }
#pragma unroll
    for (int bb = 0; bb < 4; bb++) {
        int b = ty*4 + bb;
#pragma unroll
        for (int oo = 0; oo < 4; oo++) {
            int o = tx*4 + oo;
            float v = acc[bb][oo] + g_Bg[n*D2 + o];
            float s = 1.f / (1.f + __expf(-v));
            if (o < DD)
                g_C[((size_t)n*BB + b)*D2 + DD + o] = s;
            else
                g_R[((size_t)n*BB + b)*DD + (o - DD)] = s;
        }
    }
}

// =====================================================================
// Update mix (R1-proven): hc = tanh([C|H1|H2]_n @ Wu_n + Bu)
// h = r*x + (1-r)*hc -> d_out (B,N,D)
// =====================================================================
#define JLDU 385
__global__ __launch_bounds__(256) void update_mix_kernel(float* __restrict__ out) {
    extern __shared__ float sm[];
    float* Ws = sm;
    float* Av = sm + PU;
    const int n = blockIdx.x;
    const int tid = threadIdx.x;

    const float4* wsrc = (const float4*)(g_Wu + (size_t)n * PU);
    float4* wdst = (float4*)Ws;
    for (int i = tid; i < PU/4; i += 256) wdst[i] = wsrc[i];

    const float* s0 = g_C  + (size_t)n * (BB*D2);
    const float* s1 = g_H1 + (size_t)n * (BB*D2);
    const float* s2 = g_H2 + (size_t)n * (BB*D2);
    for (int t = tid; t < BB*D2; t += 256) {
        int b = t >> 7, i = t & 127;
        Av[b*JLDU +   0 + i] = s0[t];
        Av[b*JLDU + 128 + i] = s1[t];
        Av[b*JLDU + 256 + i] = s2[t];
    }
    __syncthreads();

    const int tx = tid & 15;
    const int ty = tid >> 4;
    float acc[2][4] = {};
#pragma unroll 4
    for (int j = 0; j < KK*D2; j++) {
        float4 wv = *(const float4*)&Ws[j*DD + tx*4];
        float a0 = Av[(ty*2 + 0)*JLDU + j];
        float a1 = Av[(ty*2 + 1)*JLDU + j];
        acc[0][0] = fmaf(a0, wv.x, acc[0][0]); acc[0][1] = fmaf(a0, wv.y, acc[0][1]);
        acc[0][2] = fmaf(a0, wv.z, acc[0][2]); acc[0][3] = fmaf(a0, wv.w, acc[0][3]);
        acc[1][0] = fmaf(a1, wv.x, acc[1][0]); acc[1][1] = fmaf(a1, wv.y, acc[1][1]);
        acc[1][2] = fmaf(a1, wv.z, acc[1][2]); acc[1][3] = fmaf(a1, wv.w, acc[1][3]);
    }
#pragma unroll
    for (int bb = 0; bb < 2; bb++) {
        int b = ty*2 + bb;
#pragma unroll
        for (int oo = 0; oo < 4; oo++) {
            int o = tx*4 + oo;
            float v  = acc[bb][oo] + g_Bu[n*DD + o];
            float hc = tanhf(v);
            float r  = g_R [((size_t)n*BB + b)*DD + o];
            float xv = g_Xt[((size_t)n*BB + b)*DD + o];
            out[(size_t)b*(NN*DD) + (size_t)n*DD + o] = fmaf(r, xv - hc, hc);
        }
    }
}

// =====================================================================
// Launch
// =====================================================================
extern "C" void kernel_launch(void* const* d_in, const int* in_sizes, int n_in,
                              void* d_out, int out_size) {
    const float* x   = (const float*)d_in[0];
    const float* emb = (const float*)d_in[2];
    const float* gwp = (const float*)d_in[3];
    const float* gbp = (const float*)d_in[4];
    const float* uwp = (const float*)d_in[5];
    const float* ubp = (const float*)d_in[6];
    float* out = (float*)d_out;

    const int GATE_SMEM = (PG + BB*JLDG) * 4;
    const int UPD_SMEM  = (PU + BB*JLDU) * 4;
    cudaFuncSetAttribute(gate_mix_kernel,   cudaFuncAttributeMaxDynamicSharedMemorySize, GATE_SMEM);
    cudaFuncSetAttribute(update_mix_kernel, cudaFuncAttributeMaxDynamicSharedMemorySize, UPD_SMEM);
    cudaFuncSetAttribute(hgemm_kernel,      cudaFuncAttributeMaxDynamicSharedMemorySize, HG_SMEM);

    const int N4_SMALL = NN*BB*DD/4;          // 1,048,576 float4s (adj/Xt/G1)
    const int N4_BIG   = NN*BB*D2/4;          // 2,097,152 float4s (C/H1)

    adj_kernel<<<NN, 256>>>(emb);
    transpose_kernel<<<(NN*BB*16)/256, 256>>>(x);

    wgen_gate<<<dim3(PG/256, NN/256), 256>>>(emb, gwp);
    wgen_upd <<<dim3(PU/256, NN/256), 256>>>(emb, uwp);
    bgen_gate<<<(NN*D2 + 255)/256, 256>>>(emb, gbp);
    bgen_upd <<<(NN*DD + 255)/256, 256>>>(emb, ubp);

    split_kernel<<<NN*NN/4/256, 256>>>(0);                      // adj -> bAh/bAl
    split_kernel<<<N4_SMALL/256, 256>>>(1);                     // Xt  -> bXh/bXl

    hgemm_kernel<<<dim3(2048/CTN, NN/CTM), 256, HG_SMEM>>>(0);  // G1 = A@X
    split_kernel<<<N4_SMALL/256, 256>>>(2);                     // G1 -> bG1h/bG1l
    hgemm_kernel<<<dim3(2048/CTN, NN/CTM), 256, HG_SMEM>>>(1);  // G2 = 2A@G1 - X

    gate_mix_kernel<<<NN, 256, GATE_SMEM>>>();

    split_kernel<<<N4_BIG/256, 256>>>(3);                       // C  -> bCh/bCl
    hgemm_kernel<<<dim3(4096/CTN, NN/CTM), 256, HG_SMEM>>>(2);  // H1 = A@C
    split_kernel<<<N4_BIG/256, 256>>>(4);                       // H1 -> bH1h/bH1l
    hgemm_kernel<<<dim3(4096/CTN, NN/CTM), 256, HG_SMEM>>>(3);  // H2 = 2A@H1 - C

    update_mix_kernel<<<NN, 256, UPD_SMEM>>>(out);
}

// round 8
// speedup vs baseline: 1.6958x; 1.3175x over previous
#include <cuda_runtime.h>
#include <cuda_bf16.h>
#include <mma.h>
#include <math.h>
#include <stdint.h>

using namespace nvcuda;

// Problem dims (fixed by setup_inputs)
#define NN 2048   // nodes
#define BB 32     // batch
#define DD 64     // hidden dim
#define D2 128    // 2*hidden
#define EE 10     // embed dim
#define KK 3      // cheb order
#define PG (KK*DD*D2)   // 24576
#define PU (KK*D2*DD)   // 24576

// WMMA GEMM tiling: 128x256 CTA tile, 512 threads (16 warps x 32x64)
#define CTM 128
#define CTN 256
#define CTK 32
#define STAGES 3
#define A_LD 48
#define B_LD 272
#define A_TILE_B (CTM*A_LD*2)        // 12288
#define B_TILE_B (CTK*B_LD*2)        // 17408
#define STAGE_B  (2*A_TILE_B + 2*B_TILE_B)  // 59392
#define HG_SMEM  (STAGES*STAGE_B)    // 178176

// -------- device scratch (static allocation — no runtime allocs) --------
__device__ float g_adj[NN*NN];
__device__ float g_Xt [NN*BB*DD];
__device__ float g_G1 [NN*BB*DD];
__device__ float g_G2 [NN*BB*DD];
__device__ float g_R  [NN*BB*DD];
__device__ float g_C  [NN*BB*D2];
__device__ float g_H1 [NN*BB*D2];
__device__ float g_H2 [NN*BB*D2];
__device__ float g_Wg [(size_t)NN*PG];
__device__ float g_Wu [(size_t)NN*PU];
__device__ float g_Bg [NN*D2];
__device__ float g_Bu [NN*DD];

// bf16 hi/lo split operands (layouts identical to their fp32 sources)
__device__ __align__(16) __nv_bfloat16 bAh [NN*NN];
__device__ __align__(16) __nv_bfloat16 bAl [NN*NN];
__device__ __align__(16) __nv_bfloat16 bXh [NN*BB*DD];
__device__ __align__(16) __nv_bfloat16 bXl [NN*BB*DD];
__device__ __align__(16) __nv_bfloat16 bG1h[NN*BB*DD];
__device__ __align__(16) __nv_bfloat16 bG1l[NN*BB*DD];
__device__ __align__(16) __nv_bfloat16 bCh [(size_t)NN*BB*D2];
__device__ __align__(16) __nv_bfloat16 bCl [(size_t)NN*BB*D2];
__device__ __align__(16) __nv_bfloat16 bH1h[(size_t)NN*BB*D2];
__device__ __align__(16) __nv_bfloat16 bH1l[(size_t)NN*BB*D2];

// =====================================================================
// helpers
// =====================================================================
__device__ __forceinline__ uint32_t smem_u32(const void* p) {
    uint32_t a;
    asm("{ .reg .u64 t; cvta.to.shared.u64 t, %1; cvt.u32.u64 %0, t; }" : "=r"(a) : "l"(p));
    return a;
}
#define CP16(dst, src) asm volatile("cp.async.cg.shared.global [%0], [%1], 16;" :: "r"(dst), "l"(src))
#define CP_COMMIT()    asm volatile("cp.async.commit_group;")
#define CP_WAIT1()     asm volatile("cp.async.wait_group 1;")
#define CP_WAIT0()     asm volatile("cp.async.wait_group 0;")

__device__ __forceinline__ void split2(float a, float b, uint32_t& hi, uint32_t& lo) {
    __nv_bfloat16 ah = __float2bfloat16(a), bh = __float2bfloat16(b);
    float ar = a - __bfloat162float(ah), br = b - __bfloat162float(bh);
    __nv_bfloat16 al = __float2bfloat16(ar), bl = __float2bfloat16(br);
    hi = (uint32_t)__bfloat16_as_ushort(ah) | ((uint32_t)__bfloat16_as_ushort(bh) << 16);
    lo = (uint32_t)__bfloat16_as_ushort(al) | ((uint32_t)__bfloat16_as_ushort(bl) << 16);
}

// =====================================================================
// adj = softmax(relu(emb @ emb^T), axis=1) — R1-proven
// =====================================================================
__global__ __launch_bounds__(256) void adj_kernel(const float* __restrict__ emb) {
    __shared__ float row[NN];
    __shared__ float red[256];
    const int n = blockIdx.x;
    const int tid = threadIdx.x;
    float en[EE];
#pragma unroll
    for (int e = 0; e < EE; e++) en[e] = emb[n*EE + e];
    float lmax = 0.f;
    for (int m = tid; m < NN; m += 256) {
        float s = 0.f;
#pragma unroll
        for (int e = 0; e < EE; e++) s = fmaf(en[e], emb[m*EE + e], s);
        s = fmaxf(s, 0.f);
        row[m] = s;
        lmax = fmaxf(lmax, s);
    }
    red[tid] = lmax; __syncthreads();
    for (int s = 128; s > 0; s >>= 1) { if (tid < s) red[tid] = fmaxf(red[tid], red[tid+s]); __syncthreads(); }
    const float gmax = red[0];
    __syncthreads();
    float lsum = 0.f;
    for (int m = tid; m < NN; m += 256) { float v = __expf(row[m] - gmax); row[m] = v; lsum += v; }
    red[tid] = lsum; __syncthreads();
    for (int s = 128; s > 0; s >>= 1) { if (tid < s) red[tid] += red[tid+s]; __syncthreads(); }
    const float inv = 1.f / red[0];
    for (int m = tid; m < NN; m += 256) g_adj[n*NN + m] = row[m] * inv;
}

// =====================================================================
// Transpose x (B,N,D) -> Xt (N,B,D); also fill first half of candidate C
// =====================================================================
__global__ __launch_bounds__(256) void transpose_kernel(const float* __restrict__ x) {
    int idx = blockIdx.x * 256 + threadIdx.x;
    int d4 = idx & 15;
    int b  = (idx >> 4) & 31;
    int n  = idx >> 9;
    float4 v = *(const float4*)&x[((size_t)b*NN + n)*DD + d4*4];
    *(float4*)&g_Xt[((size_t)n*BB + b)*DD + d4*4] = v;
    *(float4*)&g_C [((size_t)n*BB + b)*D2 + d4*4] = v;
}

// =====================================================================
// Elementwise fp32 -> bf16 hi/lo split (linear index; layout preserved)
// sel: 0=adj, 1=Xt, 2=G1, 3=C, 4=H1
// =====================================================================
__global__ __launch_bounds__(256) void split_kernel(int sel) {
    const float* src; __nv_bfloat16 *dh, *dl;
    switch (sel) {
        case 0:  src = g_adj; dh = bAh;  dl = bAl;  break;
        case 1:  src = g_Xt;  dh = bXh;  dl = bXl;  break;
        case 2:  src = g_G1;  dh = bG1h; dl = bG1l; break;
        case 3:  src = g_C;   dh = bCh;  dl = bCl;  break;
        default: src = g_H1;  dh = bH1h; dl = bH1l; break;
    }
    size_t i = (size_t)blockIdx.x * 256 + threadIdx.x;   // float4 index
    float4 v = ((const float4*)src)[i];
    uint2 hi, lo;
    split2(v.x, v.y, hi.x, lo.x);
    split2(v.z, v.w, hi.y, lo.y);
    ((uint2*)dh)[i] = hi;
    ((uint2*)dl)[i] = lo;
}

// =====================================================================
// Per-node weight materialization — register-cached pool version.
// CRITICAL: output device symbol resolved in DEVICE code via selector
// (passing g_Wg from host passes the host shadow address — silent ATS
// write to host RAM on GB300; this was the R3/R4/R6 bug).
// grid (PG/1024=24, NN/128=16), 256 threads.
// =====================================================================
__global__ __launch_bounds__(256) void wgen_kernel(int which,
                                                   const float* __restrict__ emb,
                                                   const float* __restrict__ pool) {
    float* out = (which == 0) ? g_Wg : g_Wu;
    __shared__ float es[128*EE];
    const int j4 = blockIdx.x * 256 + threadIdx.x;   // float4 index in [0, PG/4)
    const int nbase = blockIdx.y * 128;
    for (int i = threadIdx.x; i < 128*EE; i += 256)
        es[i] = emb[nbase*EE + i];
    float4 pv[EE];
#pragma unroll
    for (int e = 0; e < EE; e++) pv[e] = ((const float4*)(pool + (size_t)e*PG))[j4];
    __syncthreads();
    for (int n = 0; n < 128; n++) {
        const float* er = es + n*EE;
        float4 a = make_float4(0.f, 0.f, 0.f, 0.f);
#pragma unroll
        for (int e = 0; e < EE; e++) {
            float w = er[e];
            a.x = fmaf(w, pv[e].x, a.x); a.y = fmaf(w, pv[e].y, a.y);
            a.z = fmaf(w, pv[e].z, a.z); a.w = fmaf(w, pv[e].w, a.w);
        }
        ((float4*)(out + (size_t)(nbase + n)*PG))[j4] = a;
    }
}

__device__ __forceinline__ void bgen_body(const float* __restrict__ emb,
                                          const float* __restrict__ bpool,
                                          float* __restrict__ out, int P) {
    int idx = blockIdx.x * 256 + threadIdx.x;
    if (idx >= NN * P) return;
    int n = idx / P, p = idx - n * P;
    float acc = 0.f;
#pragma unroll
    for (int e = 0; e < EE; e++) acc = fmaf(emb[n*EE + e], bpool[e*P + p], acc);
    out[idx] = acc;
}
__global__ __launch_bounds__(256) void bgen_gate(const float* emb, const float* bp) { bgen_body(emb, bp, g_Bg, D2); }
__global__ __launch_bounds__(256) void bgen_upd (const float* emb, const float* bp) { bgen_body(emb, bp, g_Bu, DD); }

// =====================================================================
// WMMA bf16-split GEMM: Out = alpha*(A@B) + beta*Cs
// 128x256 CTA tile, 512 threads (16 warps, 32x64 each), 3-stage cp.async
// =====================================================================
__global__ __launch_bounds__(512, 1) void hgemm_kernel(int which) {
    const __nv_bfloat16 *gBh, *gBl;
    float* Out; const float* Cs; float alpha, beta; int Ncols;
    switch (which) {
        case 0:  gBh = bXh;  gBl = bXl;  Out = g_G1; Cs = nullptr; alpha = 1.f; beta =  0.f; Ncols = 2048; break;
        case 1:  gBh = bG1h; gBl = bG1l; Out = g_G2; Cs = g_Xt;    alpha = 2.f; beta = -1.f; Ncols = 2048; break;
        case 2:  gBh = bCh;  gBl = bCl;  Out = g_H1; Cs = nullptr; alpha = 1.f; beta =  0.f; Ncols = 4096; break;
        default: gBh = bH1h; gBl = bH1l; Out = g_H2; Cs = g_C;     alpha = 2.f; beta = -1.f; Ncols = 4096; break;
    }
    extern __shared__ __align__(16) char smem[];
    const uint32_t sb = smem_u32(smem);
    const int tid  = threadIdx.x;
    const int lane = tid & 31;
    const int wid  = tid >> 5;           // 0..15
    const int wm   = (wid & 3) * 32;     // 0,32,64,96
    const int wn   = (wid >> 2) * 64;    // 0,64,128,192
    const int mBase = blockIdx.y * CTM;
    const int nBase = blockIdx.x * CTN;

    const int aRow = tid >> 2,  aC = tid & 3;
    const int bRow = tid >> 5,  bC = tid & 31;
    auto load_stage = [&](int it, int s) {
        const int k0 = it * CTK;
        const uint32_t st = sb + s * STAGE_B;
        {
            uint32_t d = st + aRow*(A_LD*2) + aC*16;
            size_t g = (size_t)(mBase + aRow)*NN + k0 + aC*8;
            CP16(d,            bAh + g);
            CP16(d + A_TILE_B, bAl + g);
        }
#pragma unroll
        for (int i = 0; i < 2; i++) {
            int row = bRow + i*16;
            uint32_t d = st + 2*A_TILE_B + row*(B_LD*2) + bC*16;
            size_t g = (size_t)(k0 + row)*Ncols + nBase + bC*8;
            CP16(d,            gBh + g);
            CP16(d + B_TILE_B, gBl + g);
        }
        CP_COMMIT();
    };

    wmma::fragment<wmma::accumulator, 16, 16, 16, float> acc[2][4];
#pragma unroll
    for (int mi = 0; mi < 2; mi++)
#pragma unroll
        for (int ni = 0; ni < 4; ni++)
            wmma::fill_fragment(acc[mi][ni], 0.f);

    load_stage(0, 0);
    load_stage(1, 1);

    const int k_iters = NN / CTK;   // 64
    for (int it = 0; it < k_iters; it++) {
        const int s = it % STAGES;
        if (it + 1 < k_iters) { CP_WAIT1(); } else { CP_WAIT0(); }
        __syncthreads();
        if (it + 2 < k_iters) load_stage(it + 2, (it + 2) % STAGES);

        const __nv_bfloat16* Ah = (const __nv_bfloat16*)(smem + s*STAGE_B);
        const __nv_bfloat16* Al = Ah + CTM*A_LD;
        const __nv_bfloat16* Bh = (const __nv_bfloat16*)(smem + s*STAGE_B + 2*A_TILE_B);
        const __nv_bfloat16* Bl = Bh + CTK*B_LD;

#pragma unroll
        for (int kk = 0; kk < CTK; kk += 16) {
            wmma::fragment<wmma::matrix_a, 16, 16, 16, __nv_bfloat16, wmma::row_major> ah[2], al[2];
#pragma unroll
            for (int mi = 0; mi < 2; mi++) {
                wmma::load_matrix_sync(ah[mi], Ah + (wm + mi*16)*A_LD + kk, A_LD);
                wmma::load_matrix_sync(al[mi], Al + (wm + mi*16)*A_LD + kk, A_LD);
            }
#pragma unroll
            for (int ni = 0; ni < 4; ni++) {
                wmma::fragment<wmma::matrix_b, 16, 16, 16, __nv_bfloat16, wmma::row_major> bh, bl;
                wmma::load_matrix_sync(bh, Bh + kk*B_LD + wn + ni*16, B_LD);
                wmma::load_matrix_sync(bl, Bl + kk*B_LD + wn + ni*16, B_LD);
#pragma unroll
                for (int mi = 0; mi < 2; mi++) {
                    wmma::mma_sync(acc[mi][ni], ah[mi], bh, acc[mi][ni]);
                    wmma::mma_sync(acc[mi][ni], al[mi], bh, acc[mi][ni]);
                    wmma::mma_sync(acc[mi][ni], ah[mi], bl, acc[mi][ni]);
                }
            }
        }
        __syncthreads();
    }

    // ---- epilogue via smem staging (documented row-major layout) ----
    __syncthreads();
    float* stage = (float*)smem + wid * (32*64);   // 16 warps x 8KB = 128KB
#pragma unroll
    for (int mi = 0; mi < 2; mi++)
#pragma unroll
        for (int ni = 0; ni < 4; ni++) {
            if (alpha != 1.f) {
#pragma unroll
                for (int e = 0; e < acc[mi][ni].num_elements; e++)
                    acc[mi][ni].x[e] *= alpha;
            }
            wmma::store_matrix_sync(stage + mi*16*64 + ni*16, acc[mi][ni], 64, wmma::mem_row_major);
        }
    __syncwarp();

    const int col = nBase + wn + lane*2;
    for (int r = 0; r < 32; r++) {
        const int row = mBase + wm + r;
        float2 v = *(const float2*)&stage[r*64 + lane*2];
        const size_t off = (size_t)row*Ncols + col;
        if (Cs) {
            float2 cv = *(const float2*)&Cs[off];
            v.x = fmaf(beta, cv.x, v.x);
            v.y = fmaf(beta, cv.y, v.y);
        }
        *(float2*)&Out[off] = v;
    }
}

// =====================================================================
// Gate mix (R1-proven): zr = [Xt|G1|G2]_n @ Wg_n + Bg; sigmoid
// =====================================================================
#define JLDG 193
__global__ __launch_bounds__(256) void gate_mix_kernel() {
    extern __shared__ float sm[];
    float* Ws = sm;
    float* Av = sm + PG;
    const int n = blockIdx.x;
    const int tid = threadIdx.x;

    const float4* wsrc = (const float4*)(g_Wg + (size_t)n * PG);
    float4* wdst = (float4*)Ws;
    for (int i = tid; i < PG/4; i += 256) wdst[i] = wsrc[i];

    const float* s0 = g_Xt + (size_t)n * (BB*DD);
    const float* s1 = g_G1 + (size_t)n * (BB*DD);
    const float* s2 = g_G2 + (size_t)n * (BB*DD);
    for (int t = tid; t < BB*DD; t += 256) {
        int b = t >> 6, i = t & 63;
        Av[b*JLDG +   0 + i] = s0[t];
        Av[b*JLDG +  64 + i] = s1[t];
        Av[b*JLDG + 128 + i] = s2[t];
    }
    __syncthreads();

    const int tx = tid & 31;
    const int ty = tid >> 5;
    float acc[4][4] = {};
#pragma unroll 4
    for (int j = 0; j < KK*DD; j++) {
        float4 wv = *(const float4*)&Ws[j*D2 + tx*4];
        float a0 = Av[(ty*4 + 0)*JLDG + j];
        float a1 = Av[(ty*4 + 1)*JLDG + j];
        float a2 = Av[(ty*4 + 2)*JLDG + j];
        float a3 = Av[(ty*4 + 3)*JLDG + j];
        acc[0][0] = fmaf(a0, wv.x, acc[0][0]); acc[0][1] = fmaf(a0, wv.y, acc[0][1]);
        acc[0][2] = fmaf(a0, wv.z, acc[0][2]); acc[0][3] = fmaf(a0, wv.w, acc[0][3]);
        acc[1][0] = fmaf(a1, wv.x, acc[1][0]); acc[1][1] = fmaf(a1, wv.y, acc[1][1]);
        acc[1][2] = fmaf(a1, wv.z, acc[1][2]); acc[1][3] = fmaf(a1, wv.w, acc[1][3]);
        acc[2][0] = fmaf(a2, wv.x, acc[2][0]); acc[2][1] = fmaf(a2, wv.y, acc[2][1]);
        acc[2][2] = fmaf(a2, wv.z, acc[2][2]); acc[2][3] = fmaf(a2, wv.w, acc[2][3]);
        acc[3][0] = fmaf(a3, wv.x, acc[3][0]); acc[3][1] = fmaf(a3, wv.y, acc[3][1]);
        acc[3][2] = fmaf(a3, wv.z, acc[3][2]); acc[3][3] = fmaf(a3, wv.w, acc[3][3]);
    }
#pragma unroll
    for (int bb = 0; bb < 4; bb++) {
        int b = ty*4 + bb;
#pragma unroll
        for (int oo = 0; oo < 4; oo++) {
            int o = tx*4 + oo;
            float v = acc[bb][oo] + g_Bg[n*D2 + o];
            float s = 1.f / (1.f + __expf(-v));
            if (o < DD)
                g_C[((size_t)n*BB + b)*D2 + DD + o] = s;
            else
                g_R[((size_t)n*BB + b)*DD + (o - DD)] = s;
        }
    }
}

// =====================================================================
// Update mix (R1-proven): hc = tanh([C|H1|H2]_n @ Wu_n + Bu)
// h = r*x + (1-r)*hc -> d_out (B,N,D)
// =====================================================================
#define JLDU 385
__global__ __launch_bounds__(256) void update_mix_kernel(float* __restrict__ out) {
    extern __shared__ float sm[];
    float* Ws = sm;
    float* Av = sm + PU;
    const int n = blockIdx.x;
    const int tid = threadIdx.x;

    const float4* wsrc = (const float4*)(g_Wu + (size_t)n * PU);
    float4* wdst = (float4*)Ws;
    for (int i = tid; i < PU/4; i += 256) wdst[i] = wsrc[i];

    const float* s0 = g_C  + (size_t)n * (BB*D2);
    const float* s1 = g_H1 + (size_t)n * (BB*D2);
    const float* s2 = g_H2 + (size_t)n * (BB*D2);
    for (int t = tid; t < BB*D2; t += 256) {
        int b = t >> 7, i = t & 127;
        Av[b*JLDU +   0 + i] = s0[t];
        Av[b*JLDU + 128 + i] = s1[t];
        Av[b*JLDU + 256 + i] = s2[t];
    }
    __syncthreads();

    const int tx = tid & 15;
    const int ty = tid >> 4;
    float acc[2][4] = {};
#pragma unroll 4
    for (int j = 0; j < KK*D2; j++) {
        float4 wv = *(const float4*)&Ws[j*DD + tx*4];
        float a0 = Av[(ty*2 + 0)*JLDU + j];
        float a1 = Av[(ty*2 + 1)*JLDU + j];
        acc[0][0] = fmaf(a0, wv.x, acc[0][0]); acc[0][1] = fmaf(a0, wv.y, acc[0][1]);
        acc[0][2] = fmaf(a0, wv.z, acc[0][2]); acc[0][3] = fmaf(a0, wv.w, acc[0][3]);
        acc[1][0] = fmaf(a1, wv.x, acc[1][0]); acc[1][1] = fmaf(a1, wv.y, acc[1][1]);
        acc[1][2] = fmaf(a1, wv.z, acc[1][2]); acc[1][3] = fmaf(a1, wv.w, acc[1][3]);
    }
#pragma unroll
    for (int bb = 0; bb < 2; bb++) {
        int b = ty*2 + bb;
#pragma unroll
        for (int oo = 0; oo < 4; oo++) {
            int o = tx*4 + oo;
            float v  = acc[bb][oo] + g_Bu[n*DD + o];
            float hc = tanhf(v);
            float r  = g_R [((size_t)n*BB + b)*DD + o];
            float xv = g_Xt[((size_t)n*BB + b)*DD + o];
            out[(size_t)b*(NN*DD) + (size_t)n*DD + o] = fmaf(r, xv - hc, hc);
        }
    }
}

// =====================================================================
// Launch
// =====================================================================
extern "C" void kernel_launch(void* const* d_in, const int* in_sizes, int n_in,
                              void* d_out, int out_size) {
    const float* x   = (const float*)d_in[0];
    const float* emb = (const float*)d_in[2];
    const float* gwp = (const float*)d_in[3];
    const float* gbp = (const float*)d_in[4];
    const float* uwp = (const float*)d_in[5];
    const float* ubp = (const float*)d_in[6];
    float* out = (float*)d_out;

    const int GATE_SMEM = (PG + BB*JLDG) * 4;
    const int UPD_SMEM  = (PU + BB*JLDU) * 4;
    cudaFuncSetAttribute(gate_mix_kernel,   cudaFuncAttributeMaxDynamicSharedMemorySize, GATE_SMEM);
    cudaFuncSetAttribute(update_mix_kernel, cudaFuncAttributeMaxDynamicSharedMemorySize, UPD_SMEM);
    cudaFuncSetAttribute(hgemm_kernel,      cudaFuncAttributeMaxDynamicSharedMemorySize, HG_SMEM);

    const int N4_SMALL = NN*BB*DD/4;
    const int N4_BIG   = NN*BB*D2/4;

    adj_kernel<<<NN, 256>>>(emb);
    transpose_kernel<<<(NN*BB*16)/256, 256>>>(x);
    split_kernel<<<NN*NN/4/256, 256>>>(0);                      // adj -> bAh/bAl
    split_kernel<<<N4_SMALL/256, 256>>>(1);                     // Xt  -> bXh/bXl

    hgemm_kernel<<<dim3(2048/CTN, NN/CTM), 512, HG_SMEM>>>(0);  // G1 = A@X
    split_kernel<<<N4_SMALL/256, 256>>>(2);                     // G1 -> bG1h/bG1l
    hgemm_kernel<<<dim3(2048/CTN, NN/CTM), 512, HG_SMEM>>>(1);  // G2 = 2A@G1 - X

    // weights/biases only needed by the mixes — launch after G GEMMs
    wgen_kernel<<<dim3(PG/1024, NN/128), 256>>>(0, emb, gwp);   // -> g_Wg (device-resolved)
    wgen_kernel<<<dim3(PU/1024, NN/128), 256>>>(1, emb, uwp);   // -> g_Wu (device-resolved)
    bgen_gate<<<(NN*D2 + 255)/256, 256>>>(emb, gbp);
    bgen_upd <<<(NN*DD + 255)/256, 256>>>(emb, ubp);

    gate_mix_kernel<<<NN, 256, GATE_SMEM>>>();

    split_kernel<<<N4_BIG/256, 256>>>(3);                       // C  -> bCh/bCl
    hgemm_kernel<<<dim3(4096/CTN, NN/CTM), 512, HG_SMEM>>>(2);  // H1 = A@C
    split_kernel<<<N4_BIG/256, 256>>>(4);                       // H1 -> bH1h/bH1l
    hgemm_kernel<<<dim3(4096/CTN, NN/CTM), 512, HG_SMEM>>>(3);  // H2 = 2A@H1 - C

    update_mix_kernel<<<NN, 256, UPD_SMEM>>>(out);
}